// round 16
// baseline (speedup 1.0000x reference)
#include <cuda_runtime.h>
#include <math.h>

#define NB 16      // batch
#define NV 778     // verts
#define NO 8192    // obj points
#define NG 32      // groups
#define NKNN 5     // K
#define BLK 128    // threads per block
#define VCHUNKS 7  // ceil(778/128)
#define VP (VCHUNKS * BLK)     // 896 padded vertices
#define OSPLIT 8
#define OTILE (NO / OSPLIT)    // 1024 points per block
#define NPART (VCHUNKS * NB)   // 112 partial slots
#define K5STRIDE 8             // padded slot stride (32-byte aligned vector access)

#define C3LOG2PI 5.5136313438f  // fp32(3.0 * log(2*pi))

// ---------------- device scratch (no allocation allowed) ----------------
__device__ int      g_gid[NV];
__device__ float    g_prep[NB * NG * 10];
__device__ int      g_active[NG];
__device__ unsigned g_segmin[NB * NG];
__device__ unsigned g_segmax[NB * NG];
__device__ float    g_w[NB * NV];
__device__ float    g_k5[NB * VP * OSPLIT * K5STRIDE];  // padded: float4 + float per slot
__device__ float2   g_bsi[NB * VP * OSPLIT];            // (best score, idx-as-float-bits)
__device__ float    g_part_d[NPART];
__device__ float    g_part_p[NPART];
__device__ unsigned g_ticket = 0;

#define INS5(s) do {                                                    \
    k4 = (s);                                                           \
    if (k4 < k3) { float _t = k3; k3 = k4; k4 = _t;                     \
        if (k3 < k2) { _t = k2; k2 = k3; k3 = _t;                       \
            if (k2 < k1) { _t = k1; k1 = k2; k2 = _t;                   \
                if (k1 < k0) { _t = k0; k0 = k1; k1 = _t; } } } }       \
} while (0)

// ---------------- kernel 1: parallel setup (gid | prep | active) ----------------
// grid 12 x 128: blocks 0-6 gid, blocks 7-10 Cholesky prep + seg init, block 11 active flags
__global__ void __launch_bounds__(128) k_setup(const float* __restrict__ init_verts,
                                               const float* __restrict__ init_anchors,
                                               const float* __restrict__ cg,
                                               const float* __restrict__ anchor_verts) {
    int bid = blockIdx.x;
    int t = threadIdx.x;

    if (bid < 7) {
        // ---- vertex -> group assignment ----
        int v = bid * 128 + t;
        if (v < NV) {
            float ax = init_verts[3 * v + 0];
            float ay = init_verts[3 * v + 1];
            float az = init_verts[3 * v + 2];
            float a2 = ax * ax + ay * ay + az * az;
            float best = INFINITY;
            int bi = 0;
            #pragma unroll
            for (int g = 0; g < NG; g++) {
                float bx = init_anchors[3 * g + 0];
                float by = init_anchors[3 * g + 1];
                float bz = init_anchors[3 * g + 2];
                float b2 = bx * bx + by * by + bz * bz;
                float d2 = a2 + b2 - 2.0f * (ax * bx + ay * by + az * bz);
                if (d2 < best) { best = d2; bi = g; }   // strict < : first min == argmin
            }
            g_gid[v] = bi;
        }
    } else if (bid < 11) {
        // ---- per-(b,g) Cholesky prep + segment init ----
        int idx = (bid - 7) * 128 + t;   // 0..511
        g_segmin[idx] = 0x7F800000u;     // +inf
        g_segmax[idx] = 0u;              // +0.0

        const float* c = cg + idx * 12;
        float c00 = c[3], c10 = c[6], c11 = c[7], c20 = c[9], c21 = c[10], c22 = c[11];
        float L00 = sqrtf(c00);
        float L10 = c10 / L00;
        float L20 = c20 / L00;
        float L11 = sqrtf(c11 - L10 * L10);
        float L21 = (c21 - L20 * L10) / L11;
        float L22 = sqrtf(c22 - L20 * L20 - L21 * L21);
        float hld = logf(L00) + logf(L11) + logf(L22);

        float* P = g_prep + idx * 10;
        P[0] = 1.0f / L00;
        P[1] = L10;
        P[2] = 1.0f / L11;
        P[3] = L20;
        P[4] = L21;
        P[5] = 1.0f / L22;
        P[6] = c[0] + anchor_verts[idx * 3 + 0];
        P[7] = c[1] + anchor_verts[idx * 3 + 1];
        P[8] = c[2] + anchor_verts[idx * 3 + 2];
        P[9] = hld;
    } else {
        // ---- active flags: direct per-g reduction (no atomics, no reset race) ----
        if (t < NG) {
            int act = 0;
            for (int b = 0; b < NB; b++) {
                const float* c = cg + (b * NG + t) * 12;
                #pragma unroll
                for (int i = 0; i < 12; i++) act |= (fabsf(c[i]) > 1e-9f);
            }
            g_active[t] = act;
        }
    }
}

// ---------------- kernel 2: Gaussian weights + segment min/max (champion body) ----------------
__global__ void k_weights(const float* __restrict__ verts) {
    int i = blockIdx.x * blockDim.x + threadIdx.x;
    if (i >= NB * NV) return;
    int b = i / NV;
    int v = i % NV;
    int g = g_gid[v];
    const float* P = g_prep + (b * NG + g) * 10;
    float dx = verts[3 * i + 0] - P[6];
    float dy = verts[3 * i + 1] - P[7];
    float dz = verts[3 * i + 2] - P[8];
    float y0 = dx * P[0];
    float y1 = (dy - P[1] * y0) * P[2];
    float y2 = (dz - P[3] * y0 - P[4] * y1) * P[5];
    float maha = y0 * y0 + y1 * y1 + y2 * y2;
    float logp = -0.5f * (maha + C3LOG2PI) - P[9];
    float w = expf(logp);          // strictly positive
    g_w[i] = w;
    unsigned wb = __float_as_uint(w);
    atomicMin(&g_segmin[b * NG + g], wb);
    atomicMax(&g_segmax[b * NG + g], wb);
}

// ---------------- kernel 3: split KNN + nearest-normal sweep (champion body) ----------------
__global__ void __launch_bounds__(BLK) k_main(const float* __restrict__ verts,
                                              const float* __restrict__ obj_pts,
                                              const float* __restrict__ obj_nrm) {
    __shared__ float4 sp[OTILE];   // (-2x,-2y,-2z, |p|^2) obj point
    __shared__ float4 sq[OTILE];   // (-2x,-2y,-2z, |p|^2) normal point

    int b  = blockIdx.y;
    int os = blockIdx.z;
    int vp = blockIdx.x * BLK + threadIdx.x;   // padded vertex index

    float ax = 0.f, ay = 0.f, az = 0.f;
    if (vp < NV) {
        int i = b * NV + vp;
        ax = verts[3 * i + 0];
        ay = verts[3 * i + 1];
        az = verts[3 * i + 2];
    }

    int base = os * OTILE;
    const float* OP = obj_pts + (size_t)b * NO * 3;
    const float* ON = obj_nrm + (size_t)b * NO * 6;

    for (int j = threadIdx.x; j < OTILE; j += BLK) {
        int o = base + j;
        float x = OP[3 * o + 0], y = OP[3 * o + 1], z = OP[3 * o + 2];
        sp[j] = make_float4(-2.0f * x, -2.0f * y, -2.0f * z, x * x + y * y + z * z);
        float nx = ON[6 * o + 0], ny = ON[6 * o + 1], nz = ON[6 * o + 2];
        sq[j] = make_float4(-2.0f * nx, -2.0f * ny, -2.0f * nz, nx * nx + ny * ny + nz * nz);
    }
    __syncthreads();

    float k0 = INFINITY, k1 = INFINITY, k2 = INFINITY, k3 = INFINITY, k4 = INFINITY;
    float best = INFINITY;
    int   bidx = base;

    #pragma unroll 4
    for (int j = 0; j < OTILE; j++) {
        float4 p = sp[j];   // broadcast LDS.128 — all lanes same address
        float s = fmaf(ax, p.x, fmaf(ay, p.y, fmaf(az, p.z, p.w)));
        if (s < k4) {
            k4 = s;
            if (k4 < k3) { float t = k3; k3 = k4; k4 = t;
                if (k3 < k2) { t = k2; k2 = k3; k3 = t;
                    if (k2 < k1) { t = k1; k1 = k2; k2 = t;
                        if (k1 < k0) { t = k0; k0 = k1; k1 = t; } } } }
        }
        float4 q = sq[j];
        float sn = fmaf(ax, q.x, fmaf(ay, q.y, fmaf(az, q.z, q.w)));
        if (sn < best) { best = sn; bidx = base + j; }
    }

    // padded, vectorizable partial stores
    int slot = (b * VP + vp) * OSPLIT + os;
    float* K = g_k5 + (size_t)slot * K5STRIDE;        // 32-byte aligned
    *reinterpret_cast<float4*>(K) = make_float4(k0, k1, k2, k3);
    K[4] = k4;
    g_bsi[slot] = make_float2(best, __int_as_float(bidx));
}

// ---------------- kernel 4: merge + epilogue + deterministic finish ----------------
__global__ void __launch_bounds__(BLK) k_merge(const float* __restrict__ verts,
                                               const float* __restrict__ obj_nrm,
                                               float* __restrict__ out, int out_size) {
    int b  = blockIdx.y;
    int vp = blockIdx.x * BLK + threadIdx.x;
    bool act = (vp < NV);

    int slot0 = (b * VP + vp) * OSPLIT;

    // ---- front-load ALL split partials (24 loads, one latency wave) ----
    float4 v4[OSPLIT];
    float  v1[OSPLIT];
    float2 bsi[OSPLIT];
    #pragma unroll
    for (int os = 0; os < OSPLIT; os++) {
        const float* K = g_k5 + (size_t)(slot0 + os) * K5STRIDE;
        v4[os] = *reinterpret_cast<const float4*>(K);   // LDG.128
        v1[os] = K[4];                                  // LDG.32
        bsi[os] = g_bsi[slot0 + os];                    // LDG.64
    }

    float ax = 0.f, ay = 0.f, az = 0.f, eff = 0.f;
    if (act) {
        int i = b * NV + vp;
        ax = verts[3 * i + 0];
        ay = verts[3 * i + 1];
        az = verts[3 * i + 2];
        int g = g_gid[vp];
        float w  = g_w[i];
        float mn = __uint_as_float(g_segmin[b * NG + g]);
        float mx = __uint_as_float(g_segmax[b * NG + g]);
        float wn = (w - mn) / (mx - mn);
        wn  = (wn > 0.01f) ? wn : 0.0f;     // NaN compare -> false -> 0
        eff = g_active[g] ? wn : 0.0f;
    }

    // merge 8 x top-5 (ascending split,i order preserves first-index ties)
    float k0 = INFINITY, k1 = INFINITY, k2 = INFINITY, k3 = INFINITY, k4 = INFINITY;
    #pragma unroll
    for (int os = 0; os < OSPLIT; os++) {
        float s;
        s = v4[os].x; if (s < k4) { INS5(s); }
        s = v4[os].y; if (s < k4) { INS5(s); }
        s = v4[os].z; if (s < k4) { INS5(s); }
        s = v4[os].w; if (s < k4) { INS5(s); }
        s = v1[os];   if (s < k4) { INS5(s); }
    }

    // merge argmin (strict < keeps lowest split/index on ties)
    float best = INFINITY; int bidx = 0;
    #pragma unroll
    for (int os = 0; os < OSPLIT; os++) {
        if (bsi[os].x < best) { best = bsi[os].x; bidx = __float_as_int(bsi[os].y); }
    }

    float va2 = ax * ax + ay * ay + az * az;
    float ksum = sqrtf(fmaxf(k0 + va2, 0.0f))
               + sqrtf(fmaxf(k1 + va2, 0.0f))
               + sqrtf(fmaxf(k2 + va2, 0.0f))
               + sqrtf(fmaxf(k3 + va2, 0.0f))
               + sqrtf(fmaxf(k4 + va2, 0.0f));
    float dpart = eff * ksum;

    float ppart = 0.0f;
    if (act) {
        const float* nn = obj_nrm + ((size_t)b * NO + bidx) * 6;
        float px = nn[0], py = nn[1], pz = nn[2];
        float nx = nn[3], ny = nn[4], nz = nn[5];
        float rx = px - 0.002f * nx;
        float ry = py - 0.002f * ny;
        float rz = pz - 0.002f * nz;
        float dp = nx * (ax - rx) + ny * (ay - ry) + nz * (az - rz);
        ppart = fmaxf(-dp, 0.0f);
    }

    __shared__ float2 red[BLK];
    red[threadIdx.x] = make_float2(dpart, ppart);
    __syncthreads();
    for (int s = BLK / 2; s > 0; s >>= 1) {
        if (threadIdx.x < s) {
            red[threadIdx.x].x += red[threadIdx.x + s].x;
            red[threadIdx.x].y += red[threadIdx.x + s].y;
        }
        __syncthreads();
    }

    // deterministic last-block finish (fixed-order final sum)
    if (threadIdx.x == 0) {
        int slot = blockIdx.y * VCHUNKS + blockIdx.x;
        g_part_d[slot] = red[0].x;
        g_part_p[slot] = red[0].y;
        __threadfence();
        unsigned t = atomicAdd(&g_ticket, 1);
        if (t == NPART - 1) {
            __threadfence();
            float sd = 0.0f, sp = 0.0f;
            for (int i = 0; i < NPART; i++) { sd += g_part_d[i]; sp += g_part_p[i]; }
            out[0] = sd / (float)(NB * NV * NKNN);
            if (out_size > 1) out[1] = sp / (float)(NB * NV);
            g_ticket = 0;   // reset for next graph replay
        }
    }
}

// ---------------- launch ----------------
extern "C" void kernel_launch(void* const* d_in, const int* in_sizes, int n_in,
                              void* d_out, int out_size) {
    const float* verts        = (const float*)d_in[0];  // (16,778,3)
    const float* anchor_verts = (const float*)d_in[1];  // (16,32,3)
    const float* obj_pts      = (const float*)d_in[2];  // (16,8192,3)
    const float* cg           = (const float*)d_in[3];  // (16,32,12)
    const float* obj_normals  = (const float*)d_in[4];  // (16,8192,6)
    const float* init_verts   = (const float*)d_in[5];  // (778,3)
    const float* init_anchors = (const float*)d_in[6];  // (32,3)
    (void)in_sizes; (void)n_in;

    k_setup<<<12, 128>>>(init_verts, init_anchors, cg, anchor_verts);
    k_weights<<<(NB * NV + 127) / 128, 128>>>(verts);
    dim3 grid(VCHUNKS, NB, OSPLIT);
    k_main<<<grid, BLK>>>(verts, obj_pts, obj_normals);
    dim3 mgrid(VCHUNKS, NB, 1);
    k_merge<<<mgrid, BLK>>>(verts, obj_normals, (float*)d_out, out_size);
}

// round 17
// speedup vs baseline: 1.0596x; 1.0596x over previous
#include <cuda_runtime.h>
#include <math.h>

#define NB 16      // batch
#define NV 778     // verts
#define NO 8192    // obj points
#define NG 32      // groups
#define NKNN 5     // K
#define BLK 128    // threads per block
#define VCHUNKS 7  // ceil(778/128)
#define VP (VCHUNKS * BLK)     // 896 padded vertices
#define OSPLIT 8
#define OTILE (NO / OSPLIT)    // 1024 points per block
#define NPART (VCHUNKS * NB)   // 112 partial slots

#define C3LOG2PI 5.5136313438f  // fp32(3.0 * log(2*pi))

// ---------------- device scratch (no allocation allowed) ----------------
__device__ int      g_gid[NV];
__device__ float    g_prep[NB * NG * 10];
__device__ int      g_active[NG];
__device__ unsigned g_segmin[NB * NG];
__device__ unsigned g_segmax[NB * NG];
__device__ float    g_w[NB * NV];
__device__ float    g_k5[NB * VP * OSPLIT * 5];   // per-split top-5 scores (row layout)
__device__ float    g_bs[NB * VP * OSPLIT];       // per-split best normal score
__device__ int      g_bi[NB * VP * OSPLIT];       // per-split best normal index
__device__ float    g_part_d[NPART];
__device__ float    g_part_p[NPART];
__device__ unsigned g_ticket = 0;

#define INS5(s) do {                                                    \
    k4 = (s);                                                           \
    if (k4 < k3) { float _t = k3; k3 = k4; k4 = _t;                     \
        if (k3 < k2) { _t = k2; k2 = k3; k3 = _t;                       \
            if (k2 < k1) { _t = k1; k1 = k2; k2 = _t;                   \
                if (k1 < k0) { _t = k0; k0 = k1; k1 = _t; } } } }       \
} while (0)

// ---------------- kernel 1: parallel setup (gid | prep | active) ----------------
// grid 12 x 128: blocks 0-6 gid, blocks 7-10 Cholesky prep + seg init, block 11 active flags
__global__ void __launch_bounds__(128) k_setup(const float* __restrict__ init_verts,
                                               const float* __restrict__ init_anchors,
                                               const float* __restrict__ cg,
                                               const float* __restrict__ anchor_verts) {
    int bid = blockIdx.x;
    int t = threadIdx.x;

    if (bid < 7) {
        // ---- vertex -> group assignment ----
        int v = bid * 128 + t;
        if (v < NV) {
            float ax = init_verts[3 * v + 0];
            float ay = init_verts[3 * v + 1];
            float az = init_verts[3 * v + 2];
            float a2 = ax * ax + ay * ay + az * az;
            float best = INFINITY;
            int bi = 0;
            #pragma unroll
            for (int g = 0; g < NG; g++) {
                float bx = init_anchors[3 * g + 0];
                float by = init_anchors[3 * g + 1];
                float bz = init_anchors[3 * g + 2];
                float b2 = bx * bx + by * by + bz * bz;
                float d2 = a2 + b2 - 2.0f * (ax * bx + ay * by + az * bz);
                if (d2 < best) { best = d2; bi = g; }   // strict < : first min == argmin
            }
            g_gid[v] = bi;
        }
    } else if (bid < 11) {
        // ---- per-(b,g) Cholesky prep + segment init ----
        int idx = (bid - 7) * 128 + t;   // 0..511
        g_segmin[idx] = 0x7F800000u;     // +inf
        g_segmax[idx] = 0u;              // +0.0

        const float* c = cg + idx * 12;
        float c00 = c[3], c10 = c[6], c11 = c[7], c20 = c[9], c21 = c[10], c22 = c[11];
        float L00 = sqrtf(c00);
        float L10 = c10 / L00;
        float L20 = c20 / L00;
        float L11 = sqrtf(c11 - L10 * L10);
        float L21 = (c21 - L20 * L10) / L11;
        float L22 = sqrtf(c22 - L20 * L20 - L21 * L21);
        float hld = logf(L00) + logf(L11) + logf(L22);

        float* P = g_prep + idx * 10;
        P[0] = 1.0f / L00;
        P[1] = L10;
        P[2] = 1.0f / L11;
        P[3] = L20;
        P[4] = L21;
        P[5] = 1.0f / L22;
        P[6] = c[0] + anchor_verts[idx * 3 + 0];
        P[7] = c[1] + anchor_verts[idx * 3 + 1];
        P[8] = c[2] + anchor_verts[idx * 3 + 2];
        P[9] = hld;
    } else {
        // ---- active flags: direct per-g reduction (no atomics, no reset race) ----
        if (t < NG) {
            int act = 0;
            for (int b = 0; b < NB; b++) {
                const float* c = cg + (b * NG + t) * 12;
                #pragma unroll
                for (int i = 0; i < 12; i++) act |= (fabsf(c[i]) > 1e-9f);
            }
            g_active[t] = act;
        }
    }
}

// ---------------- kernel 2: Gaussian weights + segment min/max (champion body) ----------------
__global__ void k_weights(const float* __restrict__ verts) {
    int i = blockIdx.x * blockDim.x + threadIdx.x;
    if (i >= NB * NV) return;
    int b = i / NV;
    int v = i % NV;
    int g = g_gid[v];
    const float* P = g_prep + (b * NG + g) * 10;
    float dx = verts[3 * i + 0] - P[6];
    float dy = verts[3 * i + 1] - P[7];
    float dz = verts[3 * i + 2] - P[8];
    float y0 = dx * P[0];
    float y1 = (dy - P[1] * y0) * P[2];
    float y2 = (dz - P[3] * y0 - P[4] * y1) * P[5];
    float maha = y0 * y0 + y1 * y1 + y2 * y2;
    float logp = -0.5f * (maha + C3LOG2PI) - P[9];
    float w = expf(logp);          // strictly positive
    g_w[i] = w;
    unsigned wb = __float_as_uint(w);
    atomicMin(&g_segmin[b * NG + g], wb);
    atomicMax(&g_segmax[b * NG + g], wb);
}

// ---------------- kernel 3: split sweeps, one sweep type per block ----------------
// grid z in [0,16): z<8 -> KNN sweep over obj_pts split z; z>=8 -> argmin sweep over normals split z-8.
// Halves smem per block (16 KB) -> 13 blocks/SM vs 6: doubles latency-hiding warps per SMSP.
__global__ void __launch_bounds__(BLK) k_main(const float* __restrict__ verts,
                                              const float* __restrict__ obj_pts,
                                              const float* __restrict__ obj_nrm) {
    __shared__ float4 sp[OTILE];   // (-2x,-2y,-2z, |p|^2)

    int b  = blockIdx.y;
    int z  = blockIdx.z;
    int vp = blockIdx.x * BLK + threadIdx.x;   // padded vertex index

    float ax = 0.f, ay = 0.f, az = 0.f;
    if (vp < NV) {
        int i = b * NV + vp;
        ax = verts[3 * i + 0];
        ay = verts[3 * i + 1];
        az = verts[3 * i + 2];
    }

    if (z < OSPLIT) {
        // ================= KNN sweep over obj_pts =================
        int os = z;
        int base = os * OTILE;
        const float* OP = obj_pts + (size_t)b * NO * 3;

        for (int j = threadIdx.x; j < OTILE; j += BLK) {
            int o = base + j;
            float x = OP[3 * o + 0], y = OP[3 * o + 1], zz = OP[3 * o + 2];
            sp[j] = make_float4(-2.0f * x, -2.0f * y, -2.0f * zz, x * x + y * y + zz * zz);
        }
        __syncthreads();

        float k0 = INFINITY, k1 = INFINITY, k2 = INFINITY, k3 = INFINITY, k4 = INFINITY;

        #pragma unroll 4
        for (int j = 0; j < OTILE; j++) {
            float4 p = sp[j];   // broadcast LDS.128 — all lanes same address
            float s = fmaf(ax, p.x, fmaf(ay, p.y, fmaf(az, p.z, p.w)));
            if (s < k4) {
                k4 = s;
                if (k4 < k3) { float t = k3; k3 = k4; k4 = t;
                    if (k3 < k2) { t = k2; k2 = k3; k3 = t;
                        if (k2 < k1) { t = k1; k1 = k2; k2 = t;
                            if (k1 < k0) { t = k0; k0 = k1; k1 = t; } } } }
            }
        }

        int slot = (b * VP + vp) * OSPLIT + os;
        float* K = g_k5 + slot * 5;
        K[0] = k0; K[1] = k1; K[2] = k2; K[3] = k3; K[4] = k4;
    } else {
        // ================= argmin sweep over obj_normals[:, :3] =================
        int os = z - OSPLIT;
        int base = os * OTILE;
        const float* ON = obj_nrm + (size_t)b * NO * 6;

        for (int j = threadIdx.x; j < OTILE; j += BLK) {
            int o = base + j;
            float nx = ON[6 * o + 0], ny = ON[6 * o + 1], nz = ON[6 * o + 2];
            sp[j] = make_float4(-2.0f * nx, -2.0f * ny, -2.0f * nz, nx * nx + ny * ny + nz * nz);
        }
        __syncthreads();

        float best = INFINITY;
        int   bidx = base;

        #pragma unroll 4
        for (int j = 0; j < OTILE; j++) {
            float4 q = sp[j];   // broadcast LDS.128
            float sn = fmaf(ax, q.x, fmaf(ay, q.y, fmaf(az, q.z, q.w)));
            if (sn < best) { best = sn; bidx = base + j; }
        }

        int slot = (b * VP + vp) * OSPLIT + os;
        g_bs[slot] = best;
        g_bi[slot] = bidx;
    }
}

// ---------------- kernel 4: merge + epilogue + deterministic finish (champion body) ----------------
__global__ void __launch_bounds__(BLK) k_merge(const float* __restrict__ verts,
                                               const float* __restrict__ obj_nrm,
                                               float* __restrict__ out, int out_size) {
    int b  = blockIdx.y;
    int vp = blockIdx.x * BLK + threadIdx.x;
    bool act = (vp < NV);

    float ax = 0.f, ay = 0.f, az = 0.f, eff = 0.f;
    if (act) {
        int i = b * NV + vp;
        ax = verts[3 * i + 0];
        ay = verts[3 * i + 1];
        az = verts[3 * i + 2];
        int g = g_gid[vp];
        float w  = g_w[i];
        float mn = __uint_as_float(g_segmin[b * NG + g]);
        float mx = __uint_as_float(g_segmax[b * NG + g]);
        float wn = (w - mn) / (mx - mn);
        wn  = (wn > 0.01f) ? wn : 0.0f;     // NaN compare -> false -> 0
        eff = g_active[g] ? wn : 0.0f;
    }

    int slot0 = (b * VP + vp) * OSPLIT;

    // merge 8 x top-5 (ascending split order preserves first-index ties)
    float k0 = INFINITY, k1 = INFINITY, k2 = INFINITY, k3 = INFINITY, k4 = INFINITY;
    #pragma unroll
    for (int os = 0; os < OSPLIT; os++) {
        const float* K = g_k5 + (slot0 + os) * 5;
        #pragma unroll
        for (int i = 0; i < 5; i++) {
            float s = K[i];
            if (s < k4) { INS5(s); }
        }
    }

    // merge argmin (strict < keeps lowest split/index on ties)
    float best = INFINITY; int bidx = 0;
    #pragma unroll
    for (int os = 0; os < OSPLIT; os++) {
        float s = g_bs[slot0 + os];
        if (s < best) { best = s; bidx = g_bi[slot0 + os]; }
    }

    float va2 = ax * ax + ay * ay + az * az;
    float ksum = sqrtf(fmaxf(k0 + va2, 0.0f))
               + sqrtf(fmaxf(k1 + va2, 0.0f))
               + sqrtf(fmaxf(k2 + va2, 0.0f))
               + sqrtf(fmaxf(k3 + va2, 0.0f))
               + sqrtf(fmaxf(k4 + va2, 0.0f));
    float dpart = eff * ksum;

    float ppart = 0.0f;
    if (act) {
        const float* nn = obj_nrm + ((size_t)b * NO + bidx) * 6;
        float px = nn[0], py = nn[1], pz = nn[2];
        float nx = nn[3], ny = nn[4], nz = nn[5];
        float rx = px - 0.002f * nx;
        float ry = py - 0.002f * ny;
        float rz = pz - 0.002f * nz;
        float dp = nx * (ax - rx) + ny * (ay - ry) + nz * (az - rz);
        ppart = fmaxf(-dp, 0.0f);
    }

    __shared__ float2 red[BLK];
    red[threadIdx.x] = make_float2(dpart, ppart);
    __syncthreads();
    for (int s = BLK / 2; s > 0; s >>= 1) {
        if (threadIdx.x < s) {
            red[threadIdx.x].x += red[threadIdx.x + s].x;
            red[threadIdx.x].y += red[threadIdx.x + s].y;
        }
        __syncthreads();
    }

    // deterministic last-block finish (fixed-order final sum)
    if (threadIdx.x == 0) {
        int slot = blockIdx.y * VCHUNKS + blockIdx.x;
        g_part_d[slot] = red[0].x;
        g_part_p[slot] = red[0].y;
        __threadfence();
        unsigned t = atomicAdd(&g_ticket, 1);
        if (t == NPART - 1) {
            __threadfence();
            float sd = 0.0f, sp = 0.0f;
            for (int i = 0; i < NPART; i++) { sd += g_part_d[i]; sp += g_part_p[i]; }
            out[0] = sd / (float)(NB * NV * NKNN);
            if (out_size > 1) out[1] = sp / (float)(NB * NV);
            g_ticket = 0;   // reset for next graph replay
        }
    }
}

// ---------------- launch ----------------
extern "C" void kernel_launch(void* const* d_in, const int* in_sizes, int n_in,
                              void* d_out, int out_size) {
    const float* verts        = (const float*)d_in[0];  // (16,778,3)
    const float* anchor_verts = (const float*)d_in[1];  // (16,32,3)
    const float* obj_pts      = (const float*)d_in[2];  // (16,8192,3)
    const float* cg           = (const float*)d_in[3];  // (16,32,12)
    const float* obj_normals  = (const float*)d_in[4];  // (16,8192,6)
    const float* init_verts   = (const float*)d_in[5];  // (778,3)
    const float* init_anchors = (const float*)d_in[6];  // (32,3)
    (void)in_sizes; (void)n_in;

    k_setup<<<12, 128>>>(init_verts, init_anchors, cg, anchor_verts);
    k_weights<<<(NB * NV + 127) / 128, 128>>>(verts);
    dim3 grid(VCHUNKS, NB, 2 * OSPLIT);   // z<8: KNN sweep, z>=8: argmin sweep
    k_main<<<grid, BLK>>>(verts, obj_pts, obj_normals);
    dim3 mgrid(VCHUNKS, NB, 1);
    k_merge<<<mgrid, BLK>>>(verts, obj_normals, (float*)d_out, out_size);
}